// round 16
// baseline (speedup 1.0000x reference)
#include <cuda_runtime.h>
#include <cuda_fp16.h>
#include <math.h>
#include <stdint.h>

#define BSZ  8192
#define HID  1024
#define NE   16
#define KTOP 512
#define DFF  2730
#define DFFP2 2752          // down-GEMM K padding: 86 * 32
#define UPN  2816           // up weights N padding: 22 * 128
#define GS   4

// CTA tile 128(M) x 128(N), BK=32, 128 threads = 4 warps (2M x 2N) of 64x64.
// 2 CTAs per SM; 4-stage cp.async ring (R12 proven config).
#define NSTG 4
#define A_STG 8192          // 128 m * 32 k * 2B
#define B_STG 8192          // 32 k * 128 n * 2B
#define SMB  (NSTG * A_STG)
#define SMEM_TOTAL (NSTG * (A_STG + B_STG))   // 65536

// ---- scratch (device globals; no allocations allowed) ----
__device__ float g_ST[NE * BSZ];
__device__ int   g_idx[NE * KTOP];
__device__ float g_gate[NE * KTOP];
__device__ __align__(16) __half g_hidh[(size_t)NE * KTOP * DFFP2]; // fp16 silu(up), K-padded
__device__ __align__(16) __half g_xh[(size_t)BSZ * HID];           // fp16 x
__device__ __align__(16) __half g_upwh[(size_t)NE * HID * UPN];    // fp16 up_w, N-padded rows
__device__ __align__(16) __half g_dwh[(size_t)(NE / GS) * DFF * HID]; // fp16 down_w

// ---------------------------------------------------------------------------
__device__ __forceinline__ uint32_t swz(uint32_t b) { return b ^ ((b >> 3) & 0x70); }
__device__ __forceinline__ uint32_t s2u(const void* p) {
  return (uint32_t)__cvta_generic_to_shared(p);
}
__device__ __forceinline__ void cpa16(uint32_t dst, const void* src) {
  asm volatile("cp.async.ca.shared.global [%0], [%1], 16;\n" :: "r"(dst), "l"(src));
}
__device__ __forceinline__ void cpa16p(uint32_t dst, const void* src, int ok) {
  int sz = ok ? 16 : 0;
  asm volatile("cp.async.ca.shared.global [%0], [%1], 16, %2;\n"
               :: "r"(dst), "l"(src), "r"(sz));
}
#define CPA_COMMIT() asm volatile("cp.async.commit_group;\n" ::: "memory")
#define CPA_WAIT2()  asm volatile("cp.async.wait_group 2;\n" ::: "memory")

__device__ __forceinline__ void ldsm_x4(uint32_t* r, uint32_t addr) {
  asm volatile("ldmatrix.sync.aligned.m8n8.x4.shared.b16 {%0,%1,%2,%3}, [%4];"
               : "=r"(r[0]), "=r"(r[1]), "=r"(r[2]), "=r"(r[3]) : "r"(addr));
}
__device__ __forceinline__ void ldsm_x4t(uint32_t* r, uint32_t addr) {
  asm volatile("ldmatrix.sync.aligned.m8n8.x4.trans.shared.b16 {%0,%1,%2,%3}, [%4];"
               : "=r"(r[0]), "=r"(r[1]), "=r"(r[2]), "=r"(r[3]) : "r"(addr));
}
__device__ __forceinline__ void mma_f16(float* c, const uint32_t* a,
                                        uint32_t b0, uint32_t b1) {
  asm volatile(
      "mma.sync.aligned.m16n8k16.row.col.f32.f16.f16.f32 "
      "{%0,%1,%2,%3}, {%4,%5,%6,%7}, {%8,%9}, {%0,%1,%2,%3};\n"
      : "+f"(c[0]), "+f"(c[1]), "+f"(c[2]), "+f"(c[3])
      : "r"(a[0]), "r"(a[1]), "r"(a[2]), "r"(a[3]), "r"(b0), "r"(b1));
}
__device__ __forceinline__ void red_add_v2(float* p, float v0, float v1) {
  asm volatile("red.global.add.v2.f32 [%0], {%1, %2};"
               :: "l"(p), "f"(v0), "f"(v1) : "memory");
}

// ---------------------------------------------------------------------------
__global__ void zero_kernel(float* __restrict__ out, int n) {
  int i = blockIdx.x * blockDim.x + threadIdx.x;
  int stride = gridDim.x * blockDim.x;
  float4* o4 = (float4*)out;
  int n4 = n >> 2;
  float4 z = make_float4(0.f, 0.f, 0.f, 0.f);
  for (int j = i; j < n4; j += stride) o4[j] = z;
}

// ---------------------------------------------------------------------------
// Fused router + x->fp16 convert: one warp per token, single pass over x.
// Router math is exact fp32, identical to the reference order of ops.
__global__ __launch_bounds__(256) void router_cvt_kernel(
    const float* __restrict__ x, const float* __restrict__ rw,
    const float* __restrict__ rb) {
  int gw = (blockIdx.x * blockDim.x + threadIdx.x) >> 5;
  int lane = threadIdx.x & 31;
  if (gw >= BSZ) return;
  const float* xr = x + (size_t)gw * HID;
  __half* dh = g_xh + (size_t)gw * HID;

  float acc[NE];
#pragma unroll
  for (int e = 0; e < NE; e++) acc[e] = 0.f;

#pragma unroll
  for (int it = 0; it < 8; it++) {
    int h = it * 128 + lane * 4;
    float4 xv = *(const float4*)(xr + h);
    // convert + store fp16 (8B per lane, coalesced)
    __half2 h0 = __floats2half2_rn(xv.x, xv.y);
    __half2 h1 = __floats2half2_rn(xv.z, xv.w);
    uint2 u;
    u.x = *(uint32_t*)&h0;
    u.y = *(uint32_t*)&h1;
    *(uint2*)(dh + h) = u;
    // router accumulate over the same 4 h-positions
    float xs[4] = {xv.x, xv.y, xv.z, xv.w};
#pragma unroll
    for (int qq = 0; qq < 4; qq++) {
      const float4* w4 = (const float4*)(rw + (size_t)(h + qq) * NE);
#pragma unroll
      for (int q = 0; q < 4; q++) {
        float4 w = w4[q];
        acc[q * 4 + 0] += xs[qq] * w.x;
        acc[q * 4 + 1] += xs[qq] * w.y;
        acc[q * 4 + 2] += xs[qq] * w.z;
        acc[q * 4 + 3] += xs[qq] * w.w;
      }
    }
  }
#pragma unroll
  for (int e = 0; e < NE; e++) {
#pragma unroll
    for (int off = 16; off > 0; off >>= 1)
      acc[e] += __shfl_xor_sync(0xffffffffu, acc[e], off);
  }
  if (lane == 0) {
    float mx = -1e30f;
#pragma unroll
    for (int e = 0; e < NE; e++) { acc[e] += rb[e]; mx = fmaxf(mx, acc[e]); }
    float sum = 0.f;
#pragma unroll
    for (int e = 0; e < NE; e++) { acc[e] = expf(acc[e] - mx); sum += acc[e]; }
    float inv = 1.f / sum;
#pragma unroll
    for (int e = 0; e < NE; e++) g_ST[e * BSZ + gw] = acc[e] * inv;
  }
}

__global__ void cvt_upwh_kernel(const float* __restrict__ upw) {
  int row = blockIdx.x;  // e*HID + k
  const float2* s = (const float2*)(upw + (size_t)row * DFF);
  __half2* d = (__half2*)(g_upwh + (size_t)row * UPN);
  for (int j = threadIdx.x; j < UPN / 2; j += 256) {
    __half2 h = __float2half2_rn(0.f);
    if (j < DFF / 2) { float2 v = s[j]; h = __floats2half2_rn(v.x, v.y); }
    d[j] = h;
  }
}

__global__ void cvt_dwh_kernel(const float* __restrict__ dw) {
  size_t row = blockIdx.x;  // grp*DFF + k
  const float2* s = (const float2*)(dw + row * HID);
  __half2* d = (__half2*)(g_dwh + row * HID);
#pragma unroll
  for (int q = 0; q < 2; q++) {
    int j = threadIdx.x + q * 256;
    float2 v = s[j];
    d[j] = __floats2half2_rn(v.x, v.y);
  }
}

// ---------------------------------------------------------------------------
// Per-expert exact top-512 via binary search on float bit pattern.
__global__ void topk_kernel() {
  int e = blockIdx.x;
  int tid = threadIdx.x;  // 1024 threads
  const float* s = g_ST + (size_t)e * BSZ;
  unsigned loc[8];
#pragma unroll
  for (int r = 0; r < 8; r++) loc[r] = __float_as_uint(s[tid + r * 1024]);

  __shared__ int s_cnt;
  unsigned lo = 0u, hi = 0x7F800000u;
  while (lo < hi) {
    unsigned mid = lo + ((hi - lo) >> 1) + 1u;
    if (tid == 0) s_cnt = 0;
    __syncthreads();
    int c = 0;
#pragma unroll
    for (int r = 0; r < 8; r++) c += (loc[r] >= mid) ? 1 : 0;
    c = __reduce_add_sync(0xffffffffu, c);
    if ((tid & 31) == 0) atomicAdd(&s_cnt, c);
    __syncthreads();
    int tot = s_cnt;
    if (tot >= KTOP) lo = mid; else hi = mid - 1u;
    __syncthreads();
  }
  unsigned t = lo;

  __shared__ int c_gt, c_eq;
  if (tid == 0) { c_gt = 0; c_eq = 0; }
  __syncthreads();
#pragma unroll
  for (int r = 0; r < 8; r++) {
    int i = tid + r * 1024;
    if (loc[r] > t) {
      int p = atomicAdd(&c_gt, 1);
      g_idx[e * KTOP + p] = i;
      g_gate[e * KTOP + p] = __uint_as_float(loc[r]);
    }
  }
  __syncthreads();
  int base = c_gt;
#pragma unroll
  for (int r = 0; r < 8; r++) {
    int i = tid + r * 1024;
    if (loc[r] == t) {
      int p = base + atomicAdd(&c_eq, 1);
      if (p < KTOP) {
        g_idx[e * KTOP + p] = i;
        g_gate[e * KTOP + p] = __uint_as_float(t);
      }
    }
  }
}

// ---------------------------------------------------------------------------
// fp16 HMMA up GEMM: hid[e, m, :] = fp16(silu(gather(x) @ up_w[e] + up_b[e]))
// CTA 128x128, BK=32, 4 warps (2Mx2N) of 64x64, 2 CTAs/SM.
__global__ __launch_bounds__(128, 2) void up_gemm_kernel(
    const float* __restrict__ up_b) {
  extern __shared__ char smem[];
  const uint32_t sb = s2u(smem);
  const int tid = threadIdx.x;
  const int w = tid >> 5, lane = tid & 31;
  const int wm = w >> 1, wn = w & 1;
  const int g = lane >> 2, t = lane & 3;
  const int e = blockIdx.z, n0 = blockIdx.x * 128, m0 = blockIdx.y * 128;

  // A loader: 512 chunks of 16B, 4/thread. chunk c: m = c>>2, cb = c&3
  const int acb = tid & 3;
  const __half* asrc[4];
  uint32_t adst[4];
#pragma unroll
  for (int i = 0; i < 4; i++) {
    int c = tid + i * 128;
    int am = c >> 2;
    asrc[i] = g_xh + (size_t)g_idx[e * KTOP + m0 + am] * HID + acb * 8;
    adst[i] = sb + swz(am * 64 + acb * 16);
  }

  // B loader: 512 chunks of 16B, 4/thread. chunk c: k = c>>4, cr = c&15
  const __half* bsrc[4];
  uint32_t bdst[4];
#pragma unroll
  for (int i = 0; i < 4; i++) {
    int c = tid + i * 128;
    int k = c >> 4, cr = c & 15;
    bsrc[i] = g_upwh + ((size_t)e * HID + k) * UPN + n0 + cr * 8;
    bdst[i] = sb + SMB + (uint32_t)(k * 256 + ((cr ^ (k & 7)) * 16));
  }

#define UP_LOAD(slot, ktl)                                                    \
  do {                                                                        \
    _Pragma("unroll") for (int i = 0; i < 4; i++)                             \
        cpa16(adst[i] + (slot) * A_STG, asrc[i] + (ktl) * 32);                \
    _Pragma("unroll") for (int i = 0; i < 4; i++)                             \
        cpa16(bdst[i] + (slot) * B_STG, bsrc[i] + (size_t)(ktl) * 32 * UPN);  \
    CPA_COMMIT();                                                             \
  } while (0)

  // fragment address precompute
  uint32_t a_off[4][2];
#pragma unroll
  for (int mt = 0; mt < 4; mt++)
#pragma unroll
    for (int ks = 0; ks < 2; ks++)
      a_off[mt][ks] =
          swz((wm * 64 + mt * 16 + (lane & 15)) * 64 + ks * 32 + (lane >> 4) * 16);
  const int krow = ((lane >> 3) & 1) * 8 + (lane & 7);
  const uint32_t b_k[2] = {(uint32_t)(krow * 256), (uint32_t)((krow + 16) * 256)};
  uint32_t b_co[4];
#pragma unroll
  for (int nt2 = 0; nt2 < 4; nt2++)
    b_co[nt2] = ((uint32_t)((wn * 8 + nt2 * 2 + (lane >> 4)) ^ (lane & 7))) * 16;

  float acc[4][8][4];
#pragma unroll
  for (int mt = 0; mt < 4; mt++)
#pragma unroll
    for (int nt = 0; nt < 8; nt++)
#pragma unroll
      for (int r = 0; r < 4; r++) acc[mt][nt][r] = 0.f;

  UP_LOAD(0, 0);
  UP_LOAD(1, 1);
  UP_LOAD(2, 2);

  const int KT = HID / 32;  // 32
  for (int kt = 0; kt < KT; kt++) {
    CPA_WAIT2();
    __syncthreads();
    if (kt + 3 < KT) UP_LOAD((kt + 3) & 3, kt + 3); else CPA_COMMIT();

    const uint32_t ab = sb + (kt & 3) * A_STG;
    const uint32_t bb = sb + SMB + (kt & 3) * B_STG;
#pragma unroll
    for (int ks = 0; ks < 2; ks++) {
      uint32_t af[4][4], bf[4][4];
#pragma unroll
      for (int mt = 0; mt < 4; mt++) ldsm_x4(af[mt], ab + a_off[mt][ks]);
#pragma unroll
      for (int nt2 = 0; nt2 < 4; nt2++) ldsm_x4t(bf[nt2], bb + b_k[ks] + b_co[nt2]);
#pragma unroll
      for (int mt = 0; mt < 4; mt++)
#pragma unroll
        for (int nt2 = 0; nt2 < 4; nt2++) {
          mma_f16(acc[mt][nt2 * 2 + 0], af[mt], bf[nt2][0], bf[nt2][1]);
          mma_f16(acc[mt][nt2 * 2 + 1], af[mt], bf[nt2][2], bf[nt2][3]);
        }
    }
  }
#undef UP_LOAD

  // epilogue: bias + silu, store fp16 padded rows
  const float* bias = up_b + (size_t)e * DFF;
#pragma unroll
  for (int mt = 0; mt < 4; mt++) {
#pragma unroll
    for (int p = 0; p < 2; p++) {
      int m = m0 + wm * 64 + mt * 16 + g + p * 8;
      __half* hrow = g_hidh + ((size_t)e * KTOP + m) * DFFP2;
#pragma unroll
      for (int nt = 0; nt < 8; nt++) {
        int n = n0 + wn * 64 + nt * 8 + 2 * t;
        if (n >= DFFP2) continue;
        float v0 = 0.f, v1 = 0.f;
        if (n < DFF) {  // DFF even: n+1 < DFF too
          float h0 = acc[mt][nt][p * 2 + 0] + bias[n];
          float h1 = acc[mt][nt][p * 2 + 1] + bias[n + 1];
          v0 = h0 / (1.f + expf(-h0));
          v1 = h1 / (1.f + expf(-h1));
        }
        *(__half2*)(hrow + n) = __floats2half2_rn(v0, v1);
      }
    }
  }
}

// ---------------------------------------------------------------------------
// fp16 HMMA down GEMM: out[idx[e,m],:] += gate * (hid @ down_w[e/GS] + db)
__global__ __launch_bounds__(128, 2) void down_gemm_kernel(
    const float* __restrict__ down_b, float* __restrict__ out) {
  extern __shared__ char smem[];
  const uint32_t sb = s2u(smem);
  const int tid = threadIdx.x;
  const int w = tid >> 5, lane = tid & 31;
  const int wm = w >> 1, wn = w & 1;
  const int g = lane >> 2, t = lane & 3;
  const int e = blockIdx.z, grp = e / GS;
  const int n0 = blockIdx.x * 128, m0 = blockIdx.y * 128;

  const int acb = tid & 3;
  const __half* asrc[4];
  uint32_t adst[4];
#pragma unroll
  for (int i = 0; i < 4; i++) {
    int c = tid + i * 128;
    int am = c >> 2;
    asrc[i] = g_hidh + ((size_t)e * KTOP + m0 + am) * DFFP2 + acb * 8;
    adst[i] = sb + swz(am * 64 + acb * 16);
  }

  const __half* bbase = g_dwh + (size_t)grp * DFF * HID + n0;
  int bkl[4], bcr[4];
  uint32_t bdst[4];
#pragma unroll
  for (int i = 0; i < 4; i++) {
    int c = tid + i * 128;
    bkl[i] = c >> 4; bcr[i] = c & 15;
    bdst[i] = sb + SMB + (uint32_t)(bkl[i] * 256 + ((bcr[i] ^ (bkl[i] & 7)) * 16));
  }

#define DN_LOAD(slot, ktl)                                                   \
  do {                                                                       \
    _Pragma("unroll") for (int i = 0; i < 4; i++)                            \
        cpa16(adst[i] + (slot) * A_STG, asrc[i] + (ktl) * 32);               \
    _Pragma("unroll") for (int i = 0; i < 4; i++) {                          \
      int kg = (ktl) * 32 + bkl[i];                                          \
      int ok = kg < DFF;                                                     \
      cpa16p(bdst[i] + (slot) * B_STG,                                       \
             bbase + (size_t)(ok ? kg : 0) * HID + bcr[i] * 8, ok);          \
    }                                                                        \
    CPA_COMMIT();                                                            \
  } while (0)

  uint32_t a_off[4][2];
#pragma unroll
  for (int mt = 0; mt < 4; mt++)
#pragma unroll
    for (int ks = 0; ks < 2; ks++)
      a_off[mt][ks] =
          swz((wm * 64 + mt * 16 + (lane & 15)) * 64 + ks * 32 + (lane >> 4) * 16);
  const int krow = ((lane >> 3) & 1) * 8 + (lane & 7);
  const uint32_t b_k[2] = {(uint32_t)(krow * 256), (uint32_t)((krow + 16) * 256)};
  uint32_t b_co[4];
#pragma unroll
  for (int nt2 = 0; nt2 < 4; nt2++)
    b_co[nt2] = ((uint32_t)((wn * 8 + nt2 * 2 + (lane >> 4)) ^ (lane & 7))) * 16;

  float acc[4][8][4];
#pragma unroll
  for (int mt = 0; mt < 4; mt++)
#pragma unroll
    for (int nt = 0; nt < 8; nt++)
#pragma unroll
      for (int r = 0; r < 4; r++) acc[mt][nt][r] = 0.f;

  DN_LOAD(0, 0);
  DN_LOAD(1, 1);
  DN_LOAD(2, 2);

  const int KT = DFFP2 / 32;  // 86
  for (int kt = 0; kt < KT; kt++) {
    CPA_WAIT2();
    __syncthreads();
    if (kt + 3 < KT) DN_LOAD((kt + 3) & 3, kt + 3); else CPA_COMMIT();

    const uint32_t ab = sb + (kt & 3) * A_STG;
    const uint32_t bb = sb + SMB + (kt & 3) * B_STG;
#pragma unroll
    for (int ks = 0; ks < 2; ks++) {
      uint32_t af[4][4], bf[4][4];
#pragma unroll
      for (int mt = 0; mt < 4; mt++) ldsm_x4(af[mt], ab + a_off[mt][ks]);
#pragma unroll
      for (int nt2 = 0; nt2 < 4; nt2++) ldsm_x4t(bf[nt2], bb + b_k[ks] + b_co[nt2]);
#pragma unroll
      for (int mt = 0; mt < 4; mt++)
#pragma unroll
        for (int nt2 = 0; nt2 < 4; nt2++) {
          mma_f16(acc[mt][nt2 * 2 + 0], af[mt], bf[nt2][0], bf[nt2][1]);
          mma_f16(acc[mt][nt2 * 2 + 1], af[mt], bf[nt2][2], bf[nt2][3]);
        }
    }
  }
#undef DN_LOAD

  // epilogue: gate + bias + vector scatter-add (no return -> RED)
  int tk[8];
  float gva[8];
#pragma unroll
  for (int mt = 0; mt < 4; mt++)
#pragma unroll
    for (int p = 0; p < 2; p++) {
      int m = m0 + wm * 64 + mt * 16 + g + p * 8;
      tk[mt * 2 + p] = g_idx[e * KTOP + m];
      gva[mt * 2 + p] = g_gate[e * KTOP + m];
    }
#pragma unroll
  for (int nt = 0; nt < 8; nt++) {
    int n = n0 + wn * 64 + nt * 8 + 2 * t;
    float b0 = down_b[grp * HID + n];
    float b1 = down_b[grp * HID + n + 1];
#pragma unroll
    for (int mt = 0; mt < 4; mt++)
#pragma unroll
      for (int p = 0; p < 2; p++) {
        float gv = gva[mt * 2 + p];
        float* orow = out + (size_t)tk[mt * 2 + p] * HID;
        red_add_v2(orow + n, gv * (acc[mt][nt][p * 2 + 0] + b0),
                   gv * (acc[mt][nt][p * 2 + 1] + b1));
      }
  }
}

// ---------------------------------------------------------------------------
extern "C" void kernel_launch(void* const* d_in, const int* in_sizes, int n_in,
                              void* d_out, int out_size) {
  const float* x    = (const float*)d_in[0];
  const float* rw   = (const float*)d_in[1];
  const float* rb   = (const float*)d_in[2];
  const float* up_w = (const float*)d_in[3];
  const float* up_b = (const float*)d_in[4];
  const float* dw   = (const float*)d_in[5];
  const float* db   = (const float*)d_in[6];
  float* out = (float*)d_out;

  cudaFuncSetAttribute(up_gemm_kernel,
                       cudaFuncAttributeMaxDynamicSharedMemorySize, SMEM_TOTAL);
  cudaFuncSetAttribute(down_gemm_kernel,
                       cudaFuncAttributeMaxDynamicSharedMemorySize, SMEM_TOTAL);

  zero_kernel<<<1024, 256>>>(out, out_size);
  router_cvt_kernel<<<BSZ / 8, 256>>>(x, rw, rb);
  cvt_upwh_kernel<<<NE * HID, 256>>>(up_w);
  cvt_dwh_kernel<<<(NE / GS) * DFF, 256>>>(dw);
  topk_kernel<<<NE, 1024>>>();

  dim3 gu(UPN / 128, KTOP / 128, NE);   // 22 x 4 x 16
  up_gemm_kernel<<<gu, 128, SMEM_TOTAL>>>(up_b);

  dim3 gd(HID / 128, KTOP / 128, NE);   // 8 x 4 x 16
  down_gemm_kernel<<<gd, 128, SMEM_TOTAL>>>(db, out);
}

// round 17
// speedup vs baseline: 1.1626x; 1.1626x over previous
#include <cuda_runtime.h>
#include <cuda_fp16.h>
#include <math.h>
#include <stdint.h>

#define BSZ  8192
#define HID  1024
#define NE   16
#define KTOP 512
#define DFF  2730
#define DFFP2 2752          // down-GEMM K padding: 86 * 32
#define UPN  2816           // up weights N padding: 22 * 128
#define GS   4

// CTA tile 128(M) x 128(N), BK=32, 128 threads = 4 warps (2M x 2N) of 64x64.
// 2 CTAs per SM; 4-stage cp.async ring (R12 proven config).
#define NSTG 4
#define A_STG 8192          // 128 m * 32 k * 2B
#define B_STG 8192          // 32 k * 128 n * 2B
#define SMB  (NSTG * A_STG)
#define SMEM_TOTAL (NSTG * (A_STG + B_STG))   // 65536

// ---- scratch (device globals; no allocations allowed) ----
__device__ float g_ST[NE * BSZ];
__device__ int   g_idx[NE * KTOP];
__device__ float g_gate[NE * KTOP];
__device__ __align__(16) __half g_hidh[(size_t)NE * KTOP * DFFP2]; // fp16 silu(up), K-padded
__device__ __align__(16) __half g_xh[(size_t)BSZ * HID];           // fp16 x
__device__ __align__(16) __half g_upwh[(size_t)NE * HID * UPN];    // fp16 up_w, N-padded rows
__device__ __align__(16) __half g_dwh[(size_t)(NE / GS) * DFF * HID]; // fp16 down_w

// ---------------------------------------------------------------------------
__device__ __forceinline__ uint32_t swz(uint32_t b) { return b ^ ((b >> 3) & 0x70); }
__device__ __forceinline__ uint32_t s2u(const void* p) {
  return (uint32_t)__cvta_generic_to_shared(p);
}
__device__ __forceinline__ void cpa16(uint32_t dst, const void* src) {
  asm volatile("cp.async.ca.shared.global [%0], [%1], 16;\n" :: "r"(dst), "l"(src));
}
__device__ __forceinline__ void cpa16p(uint32_t dst, const void* src, int ok) {
  int sz = ok ? 16 : 0;
  asm volatile("cp.async.ca.shared.global [%0], [%1], 16, %2;\n"
               :: "r"(dst), "l"(src), "r"(sz));
}
#define CPA_COMMIT() asm volatile("cp.async.commit_group;\n" ::: "memory")
#define CPA_WAIT2()  asm volatile("cp.async.wait_group 2;\n" ::: "memory")

__device__ __forceinline__ void ldsm_x4(uint32_t* r, uint32_t addr) {
  asm volatile("ldmatrix.sync.aligned.m8n8.x4.shared.b16 {%0,%1,%2,%3}, [%4];"
               : "=r"(r[0]), "=r"(r[1]), "=r"(r[2]), "=r"(r[3]) : "r"(addr));
}
__device__ __forceinline__ void ldsm_x4t(uint32_t* r, uint32_t addr) {
  asm volatile("ldmatrix.sync.aligned.m8n8.x4.trans.shared.b16 {%0,%1,%2,%3}, [%4];"
               : "=r"(r[0]), "=r"(r[1]), "=r"(r[2]), "=r"(r[3]) : "r"(addr));
}
__device__ __forceinline__ void mma_f16(float* c, const uint32_t* a,
                                        uint32_t b0, uint32_t b1) {
  asm volatile(
      "mma.sync.aligned.m16n8k16.row.col.f32.f16.f16.f32 "
      "{%0,%1,%2,%3}, {%4,%5,%6,%7}, {%8,%9}, {%0,%1,%2,%3};\n"
      : "+f"(c[0]), "+f"(c[1]), "+f"(c[2]), "+f"(c[3])
      : "r"(a[0]), "r"(a[1]), "r"(a[2]), "r"(a[3]), "r"(b0), "r"(b1));
}
__device__ __forceinline__ void red_add_v2(float* p, float v0, float v1) {
  asm volatile("red.global.add.v2.f32 [%0], {%1, %2};"
               :: "l"(p), "f"(v0), "f"(v1) : "memory");
}
__device__ __forceinline__ uint32_t h2u(__half2 h) { return *(uint32_t*)&h; }

// ---------------------------------------------------------------------------
__global__ void zero_kernel(float* __restrict__ out, int n) {
  int i = blockIdx.x * blockDim.x + threadIdx.x;
  int stride = gridDim.x * blockDim.x;
  float4* o4 = (float4*)out;
  int n4 = n >> 2;
  float4 z = make_float4(0.f, 0.f, 0.f, 0.f);
  for (int j = i; j < n4; j += stride) o4[j] = z;
}

// x -> fp16: 32B loads, 16B stores. One chunk of 8 per thread.
__global__ void cvt_xh_kernel(const float* __restrict__ x) {
  size_t i = (size_t)blockIdx.x * blockDim.x + threadIdx.x;  // chunk of 8
  const float4* s = (const float4*)x;
  float4 a = s[i * 2], b = s[i * 2 + 1];
  uint4 u;
  u.x = h2u(__floats2half2_rn(a.x, a.y));
  u.y = h2u(__floats2half2_rn(a.z, a.w));
  u.z = h2u(__floats2half2_rn(b.x, b.y));
  u.w = h2u(__floats2half2_rn(b.z, b.w));
  ((uint4*)g_xh)[i] = u;
}

// up_w row -> fp16 N-padded row. float2 loads (odd rows only 8B-aligned),
// 16B stores.
__global__ void cvt_upwh_kernel(const float* __restrict__ upw) {
  int row = blockIdx.x;  // e*HID + k
  const float* s = upw + (size_t)row * DFF;
  __half* d = g_upwh + (size_t)row * UPN;
  for (int c = threadIdx.x; c < UPN / 8; c += 256) {
    int n = c * 8;
    uint4 u;
    if (n + 8 <= DFF) {
      float2 v0 = *(const float2*)(s + n);
      float2 v1 = *(const float2*)(s + n + 2);
      float2 v2 = *(const float2*)(s + n + 4);
      float2 v3 = *(const float2*)(s + n + 6);
      u.x = h2u(__floats2half2_rn(v0.x, v0.y));
      u.y = h2u(__floats2half2_rn(v1.x, v1.y));
      u.z = h2u(__floats2half2_rn(v2.x, v2.y));
      u.w = h2u(__floats2half2_rn(v3.x, v3.y));
    } else {
      float v[8];
#pragma unroll
      for (int q = 0; q < 8; q++) v[q] = (n + q < DFF) ? s[n + q] : 0.f;
      u.x = h2u(__floats2half2_rn(v[0], v[1]));
      u.y = h2u(__floats2half2_rn(v[2], v[3]));
      u.z = h2u(__floats2half2_rn(v[4], v[5]));
      u.w = h2u(__floats2half2_rn(v[6], v[7]));
    }
    *(uint4*)(d + n) = u;
  }
}

// down_w -> fp16: 2 rows per block, float4 loads, 16B stores.
__global__ void cvt_dwh_kernel(const float* __restrict__ dw) {
  size_t row = blockIdx.x * 2 + (threadIdx.x >> 7);  // grp*DFF + k
  int c = threadIdx.x & 127;                          // chunk of 8 within row
  const float* s = dw + row * HID + c * 8;
  float4 a = *(const float4*)(s);
  float4 b = *(const float4*)(s + 4);
  uint4 u;
  u.x = h2u(__floats2half2_rn(a.x, a.y));
  u.y = h2u(__floats2half2_rn(a.z, a.w));
  u.z = h2u(__floats2half2_rn(b.x, b.y));
  u.w = h2u(__floats2half2_rn(b.z, b.w));
  *(uint4*)(g_dwh + row * HID + c * 8) = u;
}

// ---------------------------------------------------------------------------
// Router: one warp per token. Exact fp32 (selection must match reference).
__global__ void router_kernel(const float* __restrict__ x,
                              const float* __restrict__ rw,
                              const float* __restrict__ rb) {
  int gw = (blockIdx.x * blockDim.x + threadIdx.x) >> 5;
  int lane = threadIdx.x & 31;
  if (gw >= BSZ) return;
  const float* xr = x + (size_t)gw * HID;
  float acc[NE];
#pragma unroll
  for (int e = 0; e < NE; e++) acc[e] = 0.f;
  for (int h = lane; h < HID; h += 32) {
    float xv = xr[h];
    const float4* w4 = (const float4*)(rw + (size_t)h * NE);
#pragma unroll
    for (int q = 0; q < 4; q++) {
      float4 w = w4[q];
      acc[q * 4 + 0] += xv * w.x;
      acc[q * 4 + 1] += xv * w.y;
      acc[q * 4 + 2] += xv * w.z;
      acc[q * 4 + 3] += xv * w.w;
    }
  }
#pragma unroll
  for (int e = 0; e < NE; e++) {
#pragma unroll
    for (int off = 16; off > 0; off >>= 1)
      acc[e] += __shfl_xor_sync(0xffffffffu, acc[e], off);
  }
  if (lane == 0) {
    float mx = -1e30f;
#pragma unroll
    for (int e = 0; e < NE; e++) { acc[e] += rb[e]; mx = fmaxf(mx, acc[e]); }
    float sum = 0.f;
#pragma unroll
    for (int e = 0; e < NE; e++) { acc[e] = expf(acc[e] - mx); sum += acc[e]; }
    float inv = 1.f / sum;
#pragma unroll
    for (int e = 0; e < NE; e++) g_ST[e * BSZ + gw] = acc[e] * inv;
  }
}

// ---------------------------------------------------------------------------
// Per-expert exact top-512 via binary search on float bit pattern.
__global__ void topk_kernel() {
  int e = blockIdx.x;
  int tid = threadIdx.x;  // 1024 threads
  const float* s = g_ST + (size_t)e * BSZ;
  unsigned loc[8];
#pragma unroll
  for (int r = 0; r < 8; r++) loc[r] = __float_as_uint(s[tid + r * 1024]);

  __shared__ int s_cnt;
  unsigned lo = 0u, hi = 0x7F800000u;
  while (lo < hi) {
    unsigned mid = lo + ((hi - lo) >> 1) + 1u;
    if (tid == 0) s_cnt = 0;
    __syncthreads();
    int c = 0;
#pragma unroll
    for (int r = 0; r < 8; r++) c += (loc[r] >= mid) ? 1 : 0;
    c = __reduce_add_sync(0xffffffffu, c);
    if ((tid & 31) == 0) atomicAdd(&s_cnt, c);
    __syncthreads();
    int tot = s_cnt;
    if (tot >= KTOP) lo = mid; else hi = mid - 1u;
    __syncthreads();
  }
  unsigned t = lo;

  __shared__ int c_gt, c_eq;
  if (tid == 0) { c_gt = 0; c_eq = 0; }
  __syncthreads();
#pragma unroll
  for (int r = 0; r < 8; r++) {
    int i = tid + r * 1024;
    if (loc[r] > t) {
      int p = atomicAdd(&c_gt, 1);
      g_idx[e * KTOP + p] = i;
      g_gate[e * KTOP + p] = __uint_as_float(loc[r]);
    }
  }
  __syncthreads();
  int base = c_gt;
#pragma unroll
  for (int r = 0; r < 8; r++) {
    int i = tid + r * 1024;
    if (loc[r] == t) {
      int p = base + atomicAdd(&c_eq, 1);
      if (p < KTOP) {
        g_idx[e * KTOP + p] = i;
        g_gate[e * KTOP + p] = __uint_as_float(t);
      }
    }
  }
}

// ---------------------------------------------------------------------------
// fp16 HMMA up GEMM: hid[e, m, :] = fp16(silu(gather(x) @ up_w[e] + up_b[e]))
// CTA 128x128, BK=32, 4 warps (2Mx2N) of 64x64, 2 CTAs/SM.
__global__ __launch_bounds__(128, 2) void up_gemm_kernel(
    const float* __restrict__ up_b) {
  extern __shared__ char smem[];
  const uint32_t sb = s2u(smem);
  const int tid = threadIdx.x;
  const int w = tid >> 5, lane = tid & 31;
  const int wm = w >> 1, wn = w & 1;
  const int g = lane >> 2, t = lane & 3;
  const int e = blockIdx.z, n0 = blockIdx.x * 128, m0 = blockIdx.y * 128;

  // A loader: 512 chunks of 16B, 4/thread. chunk c: m = c>>2, cb = c&3
  const int acb = tid & 3;
  const __half* asrc[4];
  uint32_t adst[4];
#pragma unroll
  for (int i = 0; i < 4; i++) {
    int c = tid + i * 128;
    int am = c >> 2;
    asrc[i] = g_xh + (size_t)g_idx[e * KTOP + m0 + am] * HID + acb * 8;
    adst[i] = sb + swz(am * 64 + acb * 16);
  }

  // B loader: 512 chunks of 16B, 4/thread. chunk c: k = c>>4, cr = c&15
  const __half* bsrc[4];
  uint32_t bdst[4];
#pragma unroll
  for (int i = 0; i < 4; i++) {
    int c = tid + i * 128;
    int k = c >> 4, cr = c & 15;
    bsrc[i] = g_upwh + ((size_t)e * HID + k) * UPN + n0 + cr * 8;
    bdst[i] = sb + SMB + (uint32_t)(k * 256 + ((cr ^ (k & 7)) * 16));
  }

#define UP_LOAD(slot, ktl)                                                    \
  do {                                                                        \
    _Pragma("unroll") for (int i = 0; i < 4; i++)                             \
        cpa16(adst[i] + (slot) * A_STG, asrc[i] + (ktl) * 32);                \
    _Pragma("unroll") for (int i = 0; i < 4; i++)                             \
        cpa16(bdst[i] + (slot) * B_STG, bsrc[i] + (size_t)(ktl) * 32 * UPN);  \
    CPA_COMMIT();                                                             \
  } while (0)

  // fragment address precompute
  uint32_t a_off[4][2];
#pragma unroll
  for (int mt = 0; mt < 4; mt++)
#pragma unroll
    for (int ks = 0; ks < 2; ks++)
      a_off[mt][ks] =
          swz((wm * 64 + mt * 16 + (lane & 15)) * 64 + ks * 32 + (lane >> 4) * 16);
  const int krow = ((lane >> 3) & 1) * 8 + (lane & 7);
  const uint32_t b_k[2] = {(uint32_t)(krow * 256), (uint32_t)((krow + 16) * 256)};
  uint32_t b_co[4];
#pragma unroll
  for (int nt2 = 0; nt2 < 4; nt2++)
    b_co[nt2] = ((uint32_t)((wn * 8 + nt2 * 2 + (lane >> 4)) ^ (lane & 7))) * 16;

  float acc[4][8][4];
#pragma unroll
  for (int mt = 0; mt < 4; mt++)
#pragma unroll
    for (int nt = 0; nt < 8; nt++)
#pragma unroll
      for (int r = 0; r < 4; r++) acc[mt][nt][r] = 0.f;

  UP_LOAD(0, 0);
  UP_LOAD(1, 1);
  UP_LOAD(2, 2);

  const int KT = HID / 32;  // 32
  for (int kt = 0; kt < KT; kt++) {
    CPA_WAIT2();
    __syncthreads();
    if (kt + 3 < KT) UP_LOAD((kt + 3) & 3, kt + 3); else CPA_COMMIT();

    const uint32_t ab = sb + (kt & 3) * A_STG;
    const uint32_t bb = sb + SMB + (kt & 3) * B_STG;
#pragma unroll
    for (int ks = 0; ks < 2; ks++) {
      uint32_t af[4][4], bf[4][4];
#pragma unroll
      for (int mt = 0; mt < 4; mt++) ldsm_x4(af[mt], ab + a_off[mt][ks]);
#pragma unroll
      for (int nt2 = 0; nt2 < 4; nt2++) ldsm_x4t(bf[nt2], bb + b_k[ks] + b_co[nt2]);
#pragma unroll
      for (int mt = 0; mt < 4; mt++)
#pragma unroll
        for (int nt2 = 0; nt2 < 4; nt2++) {
          mma_f16(acc[mt][nt2 * 2 + 0], af[mt], bf[nt2][0], bf[nt2][1]);
          mma_f16(acc[mt][nt2 * 2 + 1], af[mt], bf[nt2][2], bf[nt2][3]);
        }
    }
  }
#undef UP_LOAD

  // epilogue: bias + silu, store fp16 padded rows
  const float* bias = up_b + (size_t)e * DFF;
#pragma unroll
  for (int mt = 0; mt < 4; mt++) {
#pragma unroll
    for (int p = 0; p < 2; p++) {
      int m = m0 + wm * 64 + mt * 16 + g + p * 8;
      __half* hrow = g_hidh + ((size_t)e * KTOP + m) * DFFP2;
#pragma unroll
      for (int nt = 0; nt < 8; nt++) {
        int n = n0 + wn * 64 + nt * 8 + 2 * t;
        if (n >= DFFP2) continue;
        float v0 = 0.f, v1 = 0.f;
        if (n < DFF) {  // DFF even: n+1 < DFF too
          float h0 = acc[mt][nt][p * 2 + 0] + bias[n];
          float h1 = acc[mt][nt][p * 2 + 1] + bias[n + 1];
          v0 = h0 / (1.f + expf(-h0));
          v1 = h1 / (1.f + expf(-h1));
        }
        *(__half2*)(hrow + n) = __floats2half2_rn(v0, v1);
      }
    }
  }
}

// ---------------------------------------------------------------------------
// fp16 HMMA down GEMM: out[idx[e,m],:] += gate * (hid @ down_w[e/GS] + db)
__global__ __launch_bounds__(128, 2) void down_gemm_kernel(
    const float* __restrict__ down_b, float* __restrict__ out) {
  extern __shared__ char smem[];
  const uint32_t sb = s2u(smem);
  const int tid = threadIdx.x;
  const int w = tid >> 5, lane = tid & 31;
  const int wm = w >> 1, wn = w & 1;
  const int g = lane >> 2, t = lane & 3;
  const int e = blockIdx.z, grp = e / GS;
  const int n0 = blockIdx.x * 128, m0 = blockIdx.y * 128;

  const int acb = tid & 3;
  const __half* asrc[4];
  uint32_t adst[4];
#pragma unroll
  for (int i = 0; i < 4; i++) {
    int c = tid + i * 128;
    int am = c >> 2;
    asrc[i] = g_hidh + ((size_t)e * KTOP + m0 + am) * DFFP2 + acb * 8;
    adst[i] = sb + swz(am * 64 + acb * 16);
  }

  const __half* bbase = g_dwh + (size_t)grp * DFF * HID + n0;
  int bkl[4], bcr[4];
  uint32_t bdst[4];
#pragma unroll
  for (int i = 0; i < 4; i++) {
    int c = tid + i * 128;
    bkl[i] = c >> 4; bcr[i] = c & 15;
    bdst[i] = sb + SMB + (uint32_t)(bkl[i] * 256 + ((bcr[i] ^ (bkl[i] & 7)) * 16));
  }

#define DN_LOAD(slot, ktl)                                                   \
  do {                                                                       \
    _Pragma("unroll") for (int i = 0; i < 4; i++)                            \
        cpa16(adst[i] + (slot) * A_STG, asrc[i] + (ktl) * 32);               \
    _Pragma("unroll") for (int i = 0; i < 4; i++) {                          \
      int kg = (ktl) * 32 + bkl[i];                                          \
      int ok = kg < DFF;                                                     \
      cpa16p(bdst[i] + (slot) * B_STG,                                       \
             bbase + (size_t)(ok ? kg : 0) * HID + bcr[i] * 8, ok);          \
    }                                                                        \
    CPA_COMMIT();                                                            \
  } while (0)

  uint32_t a_off[4][2];
#pragma unroll
  for (int mt = 0; mt < 4; mt++)
#pragma unroll
    for (int ks = 0; ks < 2; ks++)
      a_off[mt][ks] =
          swz((wm * 64 + mt * 16 + (lane & 15)) * 64 + ks * 32 + (lane >> 4) * 16);
  const int krow = ((lane >> 3) & 1) * 8 + (lane & 7);
  const uint32_t b_k[2] = {(uint32_t)(krow * 256), (uint32_t)((krow + 16) * 256)};
  uint32_t b_co[4];
#pragma unroll
  for (int nt2 = 0; nt2 < 4; nt2++)
    b_co[nt2] = ((uint32_t)((wn * 8 + nt2 * 2 + (lane >> 4)) ^ (lane & 7))) * 16;

  float acc[4][8][4];
#pragma unroll
  for (int mt = 0; mt < 4; mt++)
#pragma unroll
    for (int nt = 0; nt < 8; nt++)
#pragma unroll
      for (int r = 0; r < 4; r++) acc[mt][nt][r] = 0.f;

  DN_LOAD(0, 0);
  DN_LOAD(1, 1);
  DN_LOAD(2, 2);

  const int KT = DFFP2 / 32;  // 86
  for (int kt = 0; kt < KT; kt++) {
    CPA_WAIT2();
    __syncthreads();
    if (kt + 3 < KT) DN_LOAD((kt + 3) & 3, kt + 3); else CPA_COMMIT();

    const uint32_t ab = sb + (kt & 3) * A_STG;
    const uint32_t bb = sb + SMB + (kt & 3) * B_STG;
#pragma unroll
    for (int ks = 0; ks < 2; ks++) {
      uint32_t af[4][4], bf[4][4];
#pragma unroll
      for (int mt = 0; mt < 4; mt++) ldsm_x4(af[mt], ab + a_off[mt][ks]);
#pragma unroll
      for (int nt2 = 0; nt2 < 4; nt2++) ldsm_x4t(bf[nt2], bb + b_k[ks] + b_co[nt2]);
#pragma unroll
      for (int mt = 0; mt < 4; mt++)
#pragma unroll
        for (int nt2 = 0; nt2 < 4; nt2++) {
          mma_f16(acc[mt][nt2 * 2 + 0], af[mt], bf[nt2][0], bf[nt2][1]);
          mma_f16(acc[mt][nt2 * 2 + 1], af[mt], bf[nt2][2], bf[nt2][3]);
        }
    }
  }
#undef DN_LOAD

  // epilogue: gate + bias + vector scatter-add (no return -> RED)
  int tk[8];
  float gva[8];
#pragma unroll
  for (int mt = 0; mt < 4; mt++)
#pragma unroll
    for (int p = 0; p < 2; p++) {
      int m = m0 + wm * 64 + mt * 16 + g + p * 8;
      tk[mt * 2 + p] = g_idx[e * KTOP + m];
      gva[mt * 2 + p] = g_gate[e * KTOP + m];
    }
#pragma unroll
  for (int nt = 0; nt < 8; nt++) {
    int n = n0 + wn * 64 + nt * 8 + 2 * t;
    float b0 = down_b[grp * HID + n];
    float b1 = down_b[grp * HID + n + 1];
#pragma unroll
    for (int mt = 0; mt < 4; mt++)
#pragma unroll
      for (int p = 0; p < 2; p++) {
        float gv = gva[mt * 2 + p];
        float* orow = out + (size_t)tk[mt * 2 + p] * HID;
        red_add_v2(orow + n, gv * (acc[mt][nt][p * 2 + 0] + b0),
                   gv * (acc[mt][nt][p * 2 + 1] + b1));
      }
  }
}

// ---------------------------------------------------------------------------
extern "C" void kernel_launch(void* const* d_in, const int* in_sizes, int n_in,
                              void* d_out, int out_size) {
  const float* x    = (const float*)d_in[0];
  const float* rw   = (const float*)d_in[1];
  const float* rb   = (const float*)d_in[2];
  const float* up_w = (const float*)d_in[3];
  const float* up_b = (const float*)d_in[4];
  const float* dw   = (const float*)d_in[5];
  const float* db   = (const float*)d_in[6];
  float* out = (float*)d_out;

  cudaFuncSetAttribute(up_gemm_kernel,
                       cudaFuncAttributeMaxDynamicSharedMemorySize, SMEM_TOTAL);
  cudaFuncSetAttribute(down_gemm_kernel,
                       cudaFuncAttributeMaxDynamicSharedMemorySize, SMEM_TOTAL);

  zero_kernel<<<1024, 256>>>(out, out_size);
  cvt_xh_kernel<<<(BSZ * HID / 8) / 256, 256>>>(x);
  cvt_upwh_kernel<<<NE * HID, 256>>>(up_w);
  cvt_dwh_kernel<<<(NE / GS) * DFF / 2, 256>>>(dw);
  router_kernel<<<BSZ / 8, 256>>>(x, rw, rb);
  topk_kernel<<<NE, 1024>>>();

  dim3 gu(UPN / 128, KTOP / 128, NE);   // 22 x 4 x 16
  up_gemm_kernel<<<gu, 128, SMEM_TOTAL>>>(up_b);

  dim3 gd(HID / 128, KTOP / 128, NE);   // 8 x 4 x 16
  down_gemm_kernel<<<gd, 128, SMEM_TOTAL>>>(db, out);
}